// round 2
// baseline (speedup 1.0000x reference)
#include <cuda_runtime.h>
#include <cstdint>

// ---------------- problem constants ----------------
#define BATCH   16384
#define DIN     1408
#define DHID    256
#define DOUT    3
#define NHEADS  32

// ---------------- tiling ----------------
#define MT      128          // CTA rows
#define KT      32           // K per stage
#define NK      (DIN / KT)   // 44
#define NSTG    3
#define NTH     512          // 16 warps: 4 (M) x 4 (N)

// ---------------- smem layout (bytes, dynamic) ----------------
#define A_PAD   36           // floats per A row  (conflict-free: g*4+tig)
#define B_PAD   264          // floats per B row  (conflict-free: tig*8+g)
#define A_SZ    (MT * A_PAD * 4)            // 18432
#define B_SZ    (KT * B_PAD * 4)            // 33792
#define STG_SZ  (A_SZ + B_SZ)               // 52224
#define SM_EP   (NSTG * STG_SZ)             // 156672 : 256 x float4 table
#define SM_RED  0                           // reuse stage 0 region post-loop
#define SMEM_TOTAL (SM_EP + DHID * 16)      // 160768

// ---------------- scratch (alloc-free rule: device globals) ----------------
__device__ __align__(16) float g_Arnd[(size_t)BATCH * DIN];           // A rounded to tf32
__device__ __align__(16) float g_W1r[(size_t)NHEADS * DIN * DHID];    // W1 rounded to tf32

// ---------------- helpers ----------------
__device__ __forceinline__ uint32_t smem_u32(const void* p) {
    uint32_t a;
    asm("{ .reg .u64 t; cvta.to.shared.u64 t, %1; cvt.u32.u64 %0, t; }" : "=r"(a) : "l"(p));
    return a;
}

__device__ __forceinline__ void cp_async16(uint32_t dst, const void* src) {
    asm volatile("cp.async.cg.shared.global [%0], [%1], 16;\n" :: "r"(dst), "l"(src));
}

__device__ __forceinline__ float lds_f(uint32_t addr) {
    float v;
    asm volatile("ld.shared.f32 %0, [%1];" : "=f"(v) : "r"(addr));
    return v;
}

__device__ __forceinline__ void mma_tf32(float* d, const uint32_t* a, uint32_t b0, uint32_t b1) {
    asm volatile(
        "mma.sync.aligned.m16n8k8.row.col.f32.tf32.tf32.f32 "
        "{%0,%1,%2,%3}, {%4,%5,%6,%7}, {%8,%9}, {%0,%1,%2,%3};"
        : "+f"(d[0]), "+f"(d[1]), "+f"(d[2]), "+f"(d[3])
        : "r"(a[0]), "r"(a[1]), "r"(a[2]), "r"(a[3]), "r"(b0), "r"(b1));
}

// ---------------- prep: RN-round fp32 -> tf32 bit pattern ----------------
__global__ void k_round_tf32(const float* __restrict__ in, float* __restrict__ out, int n4) {
    int i = blockIdx.x * blockDim.x + threadIdx.x;
    if (i >= n4) return;
    float4 v = reinterpret_cast<const float4*>(in)[i];
    uint32_t r0, r1, r2, r3;
    asm("cvt.rna.tf32.f32 %0, %1;" : "=r"(r0) : "f"(v.x));
    asm("cvt.rna.tf32.f32 %0, %1;" : "=r"(r1) : "f"(v.y));
    asm("cvt.rna.tf32.f32 %0, %1;" : "=r"(r2) : "f"(v.z));
    asm("cvt.rna.tf32.f32 %0, %1;" : "=r"(r3) : "f"(v.w));
    uint4 o; o.x = r0; o.y = r1; o.z = r2; o.w = r3;
    reinterpret_cast<uint4*>(out)[i] = o;
}

// ---------------- stage loader ----------------
__device__ __forceinline__ void load_stage(uint32_t stage_base, const float* __restrict__ Ag,
                                           const float* __restrict__ Bg, int kt, int tid) {
    const float* ak = Ag + kt * KT;
#pragma unroll
    for (int i = 0; i < 2; i++) {               // A: 128 x 32 fp32 = 1024 granules
        int gi = tid + i * NTH;
        int r = gi >> 3, c = gi & 7;
        cp_async16(stage_base + r * (A_PAD * 4) + c * 16, ak + (size_t)r * DIN + c * 4);
    }
    const float* bk = Bg + (size_t)kt * KT * DHID;
#pragma unroll
    for (int i = 0; i < 4; i++) {               // B: 32 x 256 fp32 = 2048 granules
        int gi = tid + i * NTH;
        int r = gi >> 6, c = gi & 63;
        cp_async16(stage_base + A_SZ + r * (B_PAD * 4) + c * 16, bk + r * DHID + c * 4);
    }
}

// ---------------- main fused kernel ----------------
__global__ void __launch_bounds__(NTH, 1) mano_gemm(
    const float* __restrict__ b1, const float* __restrict__ W2,
    const float* __restrict__ b2, float* __restrict__ out) {
    extern __shared__ char smem[];
    const uint32_t sb = smem_u32(smem);
    const int tid = threadIdx.x;
    const int wid = tid >> 5, lane = tid & 31;
    const int g = lane >> 2, tig = lane & 3;     // groupID / threadID-in-group
    const int wm = wid & 3, wn = wid >> 2;       // warp tile: rows wm*32, cols wn*64
    const int head = blockIdx.x;                 // head-fastest: L2 reuse of A slab + all W1
    const int m0 = blockIdx.y * MT;

    const float* Ag = g_Arnd + (size_t)m0 * DIN;
    const float* Bg = g_W1r + (size_t)head * DIN * DHID;

    // epilogue table: wb[c] = {b1[c], W2[c][0], W2[c][1], W2[c][2]}
    {
        const float* b1h = b1 + head * DHID;
        const float* w2h = W2 + (size_t)head * DHID * DOUT;
        if (tid < DHID) {
            float4 v;
            v.x = b1h[tid];
            v.y = w2h[tid * 3 + 0];
            v.z = w2h[tid * 3 + 1];
            v.w = w2h[tid * 3 + 2];
            *reinterpret_cast<float4*>(smem + SM_EP + tid * 16) = v;
        }
    }

    // prologue: stages 0,1 in flight
    load_stage(sb + 0 * STG_SZ, Ag, Bg, 0, tid);
    asm volatile("cp.async.commit_group;\n");
    load_stage(sb + 1 * STG_SZ, Ag, Bg, 1, tid);
    asm volatile("cp.async.commit_group;\n");

    float acc[2][8][4];
#pragma unroll
    for (int t = 0; t < 2; t++)
#pragma unroll
        for (int j = 0; j < 8; j++)
#pragma unroll
            for (int e = 0; e < 4; e++) acc[t][j][e] = 0.f;

    for (int kt = 0; kt < NK; kt++) {
        const int buf = kt % NSTG;
        asm volatile("cp.async.wait_group 1;\n");   // stage kt landed
        __syncthreads();                            // all warps done with stage kt-1's buffer

        // prefetch stage kt+2 into buffer (kt+2)%NSTG (its old data consumed at kt-1)
        if (kt + 2 < NK)
            load_stage(sb + ((kt + 2) % NSTG) * STG_SZ, Ag, Bg, kt + 2, tid);
        asm volatile("cp.async.commit_group;\n");   // empty group ok at tail

        const uint32_t a_base = sb + buf * STG_SZ;
        const uint32_t b_base = a_base + A_SZ;
#pragma unroll
        for (int k8 = 0; k8 < 4; k8++) {
            const int kk = k8 * 8;
            uint32_t a[2][4];
#pragma unroll
            for (int t = 0; t < 2; t++) {
                int r0 = wm * 32 + t * 16 + g;
                a[t][0] = __float_as_uint(lds_f(a_base + (r0 * A_PAD + kk + tig) * 4));
                a[t][1] = __float_as_uint(lds_f(a_base + ((r0 + 8) * A_PAD + kk + tig) * 4));
                a[t][2] = __float_as_uint(lds_f(a_base + (r0 * A_PAD + kk + 4 + tig) * 4));
                a[t][3] = __float_as_uint(lds_f(a_base + ((r0 + 8) * A_PAD + kk + 4 + tig) * 4));
            }
#pragma unroll
            for (int j = 0; j < 8; j++) {
                int n = wn * 64 + j * 8 + g;
                uint32_t b0 = __float_as_uint(lds_f(b_base + ((kk + tig) * B_PAD + n) * 4));
                uint32_t b1r = __float_as_uint(lds_f(b_base + ((kk + 4 + tig) * B_PAD + n) * 4));
                mma_tf32(acc[0][j], a[0], b0, b1r);
                mma_tf32(acc[1][j], a[1], b0, b1r);
            }
        }
    }

    __syncthreads();    // done reading stage smem; safe to reuse region 0 for reduction

    // ---- fused epilogue: h = relu(acc + b1); partial[p] += h * W2[:,p] ----
    float s[2][2][3];
#pragma unroll
    for (int t = 0; t < 2; t++)
#pragma unroll
        for (int h = 0; h < 2; h++)
            s[t][h][0] = s[t][h][1] = s[t][h][2] = 0.f;

#pragma unroll
    for (int j = 0; j < 8; j++) {
#pragma unroll
        for (int e = 0; e < 2; e++) {
            const int c = wn * 64 + j * 8 + tig * 2 + e;
            const float4 wv = *reinterpret_cast<const float4*>(smem + SM_EP + c * 16);
#pragma unroll
            for (int t = 0; t < 2; t++) {
#pragma unroll
                for (int h = 0; h < 2; h++) {
                    float hv = fmaxf(acc[t][j][h * 2 + e] + wv.x, 0.f);
                    s[t][h][0] = fmaf(hv, wv.y, s[t][h][0]);
                    s[t][h][1] = fmaf(hv, wv.z, s[t][h][1]);
                    s[t][h][2] = fmaf(hv, wv.w, s[t][h][2]);
                }
            }
        }
    }

    // reduce over tig (lanes sharing a row): lane bits 0,1
#pragma unroll
    for (int t = 0; t < 2; t++)
#pragma unroll
        for (int h = 0; h < 2; h++)
#pragma unroll
            for (int p = 0; p < 3; p++) {
                float v = s[t][h][p];
                v += __shfl_xor_sync(0xffffffffu, v, 1);
                v += __shfl_xor_sync(0xffffffffu, v, 2);
                s[t][h][p] = v;
            }

    // cross-warp (wn) reduction through smem: red[wn][row][p]
    float* red = reinterpret_cast<float*>(smem + SM_RED);
    if (tig == 0) {
#pragma unroll
        for (int t = 0; t < 2; t++)
#pragma unroll
            for (int h = 0; h < 2; h++) {
                int row = wm * 32 + t * 16 + h * 8 + g;
#pragma unroll
                for (int p = 0; p < 3; p++)
                    red[(wn * MT + row) * 3 + p] = s[t][h][p];
            }
    }
    __syncthreads();

    if (tid < MT * 3) {
        int r = tid / 3, p = tid % 3;
        float v = red[(0 * MT + r) * 3 + p] + red[(1 * MT + r) * 3 + p]
                + red[(2 * MT + r) * 3 + p] + red[(3 * MT + r) * 3 + p]
                + __ldg(b2 + head * DOUT + p);
        out[(size_t)(m0 + r) * (NHEADS * DOUT) + head * DOUT + p] = v;
    }
}

// ---------------- launch ----------------
extern "C" void kernel_launch(void* const* d_in, const int* in_sizes, int n_in,
                              void* d_out, int out_size) {
    const float* total_feat = (const float*)d_in[0];
    const float* W1 = (const float*)d_in[1];
    const float* b1 = (const float*)d_in[2];
    const float* W2 = (const float*)d_in[3];
    const float* b2 = (const float*)d_in[4];
    float* out = (float*)d_out;

    float* dA;  cudaGetSymbolAddress((void**)&dA, g_Arnd);
    float* dW;  cudaGetSymbolAddress((void**)&dW, g_W1r);

    int nA4 = (BATCH * DIN) / 4;
    int nW4 = (NHEADS * DIN * DHID) / 4;
    k_round_tf32<<<(nA4 + 255) / 256, 256>>>(total_feat, dA, nA4);
    k_round_tf32<<<(nW4 + 255) / 256, 256>>>(W1, dW, nW4);

    cudaFuncSetAttribute(mano_gemm, cudaFuncAttributeMaxDynamicSharedMemorySize, SMEM_TOTAL);
    mano_gemm<<<dim3(NHEADS, BATCH / MT), NTH, SMEM_TOTAL>>>(b1, W2, b2, out);
}

// round 3
// speedup vs baseline: 1.0311x; 1.0311x over previous
#include <cuda_runtime.h>
#include <cstdint>

// ---------------- problem constants ----------------
#define BATCH   16384
#define DIN     1408
#define DHID    256
#define DOUT    3
#define NHEADS  32

// ---------------- tiling ----------------
#define MT      128          // CTA rows
#define NT      256          // CTA cols (one full head)
#define KT      32           // K per stage
#define NK      (DIN / KT)   // 44
#define NSTG    3
#define NTH     256          // 8 warps: 2 (M) x 4 (N), warp tile 64x64

// ---------------- smem layout (bytes, dynamic) ----------------
#define A_PAD   36           // floats per A row  (conflict-free)
#define B_PAD   264          // floats per B row  (conflict-free)
#define A_SZ    (MT * A_PAD * 4)            // 18432
#define B_SZ    (KT * B_PAD * 4)            // 33792
#define STG_SZ  (A_SZ + B_SZ)               // 52224
#define SM_EP   (NSTG * STG_SZ)             // 156672 : 256 x float4 table
#define SM_RED  0                           // reuse stage 0 region post-loop
#define SMEM_TOTAL (SM_EP + DHID * 16)      // 160768

// ---------------- scratch (alloc-free rule: device globals) ----------------
__device__ __align__(16) float g_Arnd[(size_t)BATCH * DIN];           // A rounded to tf32
__device__ __align__(16) float g_W1r[(size_t)NHEADS * DIN * DHID];    // W1 rounded to tf32

#define NA4 ((BATCH * DIN) / 4)
#define NW4 ((NHEADS * DIN * DHID) / 4)

// ---------------- helpers ----------------
__device__ __forceinline__ uint32_t smem_u32(const void* p) {
    uint32_t a;
    asm("{ .reg .u64 t; cvta.to.shared.u64 t, %1; cvt.u32.u64 %0, t; }" : "=r"(a) : "l"(p));
    return a;
}

__device__ __forceinline__ void cp_async16(uint32_t dst, const void* src) {
    asm volatile("cp.async.cg.shared.global [%0], [%1], 16;\n" :: "r"(dst), "l"(src));
}

__device__ __forceinline__ float lds_f(uint32_t addr) {
    float v;
    asm volatile("ld.shared.f32 %0, [%1];" : "=f"(v) : "r"(addr));
    return v;
}

__device__ __forceinline__ void mma_tf32(float* d, const uint32_t* a, uint32_t b0, uint32_t b1) {
    asm volatile(
        "mma.sync.aligned.m16n8k8.row.col.f32.tf32.tf32.f32 "
        "{%0,%1,%2,%3}, {%4,%5,%6,%7}, {%8,%9}, {%0,%1,%2,%3};"
        : "+f"(d[0]), "+f"(d[1]), "+f"(d[2]), "+f"(d[3])
        : "r"(a[0]), "r"(a[1]), "r"(a[2]), "r"(a[3]), "r"(b0), "r"(b1));
}

// ---------------- prep: RN-round fp32 -> tf32 (A and W1 in one launch) ----------------
__global__ void k_prep(const float* __restrict__ A, const float* __restrict__ W) {
    int i = blockIdx.x * blockDim.x + threadIdx.x;
    if (i >= NA4 + NW4) return;
    const float4* src;
    uint4* dst;
    if (i < NA4) {
        src = reinterpret_cast<const float4*>(A) + i;
        dst = reinterpret_cast<uint4*>(g_Arnd) + i;
    } else {
        src = reinterpret_cast<const float4*>(W) + (i - NA4);
        dst = reinterpret_cast<uint4*>(g_W1r) + (i - NA4);
    }
    float4 v = *src;
    uint4 o;
    asm("cvt.rna.tf32.f32 %0, %1;" : "=r"(o.x) : "f"(v.x));
    asm("cvt.rna.tf32.f32 %0, %1;" : "=r"(o.y) : "f"(v.y));
    asm("cvt.rna.tf32.f32 %0, %1;" : "=r"(o.z) : "f"(v.z));
    asm("cvt.rna.tf32.f32 %0, %1;" : "=r"(o.w) : "f"(v.w));
    *dst = o;
}

// ---------------- stage loader ----------------
__device__ __forceinline__ void load_stage(uint32_t stage_base, const float* __restrict__ Ag,
                                           const float* __restrict__ Bg, int kt, int tid) {
    const float* ak = Ag + kt * KT;
#pragma unroll
    for (int i = 0; i < 4; i++) {               // A: 128 x 32 fp32 = 1024 granules of 16B
        int gi = tid + i * NTH;
        int r = gi >> 3, c = gi & 7;
        cp_async16(stage_base + r * (A_PAD * 4) + c * 16, ak + (size_t)r * DIN + c * 4);
    }
    const float* bk = Bg + (size_t)kt * KT * DHID;
#pragma unroll
    for (int i = 0; i < 8; i++) {               // B: 32 x 256 fp32 = 2048 granules of 16B
        int gi = tid + i * NTH;
        int r = gi >> 6, c = gi & 63;
        cp_async16(stage_base + A_SZ + r * (B_PAD * 4) + c * 16, bk + r * DHID + c * 4);
    }
}

// ---------------- main fused kernel ----------------
__global__ void __launch_bounds__(NTH, 1) mano_gemm(
    const float* __restrict__ b1, const float* __restrict__ W2,
    const float* __restrict__ b2, float* __restrict__ out) {
    extern __shared__ char smem[];
    const uint32_t sb = smem_u32(smem);
    const int tid = threadIdx.x;
    const int wid = tid >> 5, lane = tid & 31;
    const int g = lane >> 2, tig = lane & 3;     // groupID / threadID-in-group
    const int wm = wid & 1, wn = wid >> 1;       // warp tile: rows wm*64, cols wn*64
    const int head = blockIdx.x;                 // head-fastest: L2 reuse of A slab + all W1
    const int m0 = blockIdx.y * MT;

    const float* Ag = g_Arnd + (size_t)m0 * DIN;
    const float* Bg = g_W1r + (size_t)head * DIN * DHID;

    // epilogue table: wb[c] = {b1[c], W2[c][0], W2[c][1], W2[c][2]}
    if (tid < DHID) {
        const float* b1h = b1 + head * DHID;
        const float* w2h = W2 + (size_t)head * DHID * DOUT;
        float4 v;
        v.x = b1h[tid];
        v.y = w2h[tid * 3 + 0];
        v.z = w2h[tid * 3 + 1];
        v.w = w2h[tid * 3 + 2];
        *reinterpret_cast<float4*>(smem + SM_EP + tid * 16) = v;
    }

    // prologue: stages 0,1 in flight
    load_stage(sb + 0 * STG_SZ, Ag, Bg, 0, tid);
    asm volatile("cp.async.commit_group;\n");
    load_stage(sb + 1 * STG_SZ, Ag, Bg, 1, tid);
    asm volatile("cp.async.commit_group;\n");

    float acc[4][8][4];
#pragma unroll
    for (int t = 0; t < 4; t++)
#pragma unroll
        for (int j = 0; j < 8; j++)
#pragma unroll
            for (int e = 0; e < 4; e++) acc[t][j][e] = 0.f;

    for (int kt = 0; kt < NK; kt++) {
        const int buf = kt % NSTG;
        asm volatile("cp.async.wait_group 1;\n");   // stage kt landed
        __syncthreads();                            // all warps done with stage kt-1's buffer

        // prefetch stage kt+2 into buffer (kt+2)%NSTG (its old data consumed at kt-1)
        if (kt + 2 < NK)
            load_stage(sb + ((kt + 2) % NSTG) * STG_SZ, Ag, Bg, kt + 2, tid);
        asm volatile("cp.async.commit_group;\n");   // empty group ok at tail

        const uint32_t a_base = sb + buf * STG_SZ;
        const uint32_t b_base = a_base + A_SZ;
#pragma unroll
        for (int k8 = 0; k8 < 4; k8++) {
            const int kk = k8 * 8;
            uint32_t a[4][4];
#pragma unroll
            for (int t = 0; t < 4; t++) {
                int r0 = wm * 64 + t * 16 + g;
                a[t][0] = __float_as_uint(lds_f(a_base + (r0 * A_PAD + kk + tig) * 4));
                a[t][1] = __float_as_uint(lds_f(a_base + ((r0 + 8) * A_PAD + kk + tig) * 4));
                a[t][2] = __float_as_uint(lds_f(a_base + (r0 * A_PAD + kk + 4 + tig) * 4));
                a[t][3] = __float_as_uint(lds_f(a_base + ((r0 + 8) * A_PAD + kk + 4 + tig) * 4));
            }
#pragma unroll
            for (int j = 0; j < 8; j++) {
                int n = wn * 64 + j * 8 + g;
                uint32_t b0 = __float_as_uint(lds_f(b_base + ((kk + tig) * B_PAD + n) * 4));
                uint32_t b1r = __float_as_uint(lds_f(b_base + ((kk + 4 + tig) * B_PAD + n) * 4));
#pragma unroll
                for (int t = 0; t < 4; t++)
                    mma_tf32(acc[t][j], a[t], b0, b1r);
            }
        }
    }

    __syncthreads();    // done reading stage smem; safe to reuse region 0 for reduction

    // ---- fused epilogue: h = relu(acc + b1); partial[p] += h * W2[:,p] ----
    float s[4][2][3];
#pragma unroll
    for (int t = 0; t < 4; t++)
#pragma unroll
        for (int h = 0; h < 2; h++)
            s[t][h][0] = s[t][h][1] = s[t][h][2] = 0.f;

#pragma unroll
    for (int j = 0; j < 8; j++) {
#pragma unroll
        for (int e = 0; e < 2; e++) {
            const int c = wn * 64 + j * 8 + tig * 2 + e;
            const float4 wv = *reinterpret_cast<const float4*>(smem + SM_EP + c * 16);
#pragma unroll
            for (int t = 0; t < 4; t++) {
#pragma unroll
                for (int h = 0; h < 2; h++) {
                    float hv = fmaxf(acc[t][j][h * 2 + e] + wv.x, 0.f);
                    s[t][h][0] = fmaf(hv, wv.y, s[t][h][0]);
                    s[t][h][1] = fmaf(hv, wv.z, s[t][h][1]);
                    s[t][h][2] = fmaf(hv, wv.w, s[t][h][2]);
                }
            }
        }
    }

    // reduce over tig (lanes sharing a row): lane bits 0,1
#pragma unroll
    for (int t = 0; t < 4; t++)
#pragma unroll
        for (int h = 0; h < 2; h++)
#pragma unroll
            for (int p = 0; p < 3; p++) {
                float v = s[t][h][p];
                v += __shfl_xor_sync(0xffffffffu, v, 1);
                v += __shfl_xor_sync(0xffffffffu, v, 2);
                s[t][h][p] = v;
            }

    // cross-warp (wn) reduction through smem: red[wn][row][p]
    float* red = reinterpret_cast<float*>(smem + SM_RED);
    if (tig == 0) {
#pragma unroll
        for (int t = 0; t < 4; t++)
#pragma unroll
            for (int h = 0; h < 2; h++) {
                int row = wm * 64 + t * 16 + h * 8 + g;
#pragma unroll
                for (int p = 0; p < 3; p++)
                    red[(wn * MT + row) * 3 + p] = s[t][h][p];
            }
    }
    __syncthreads();

    for (int i = tid; i < MT * 3; i += NTH) {
        int r = i / 3, p = i % 3;
        float v = red[(0 * MT + r) * 3 + p] + red[(1 * MT + r) * 3 + p]
                + red[(2 * MT + r) * 3 + p] + red[(3 * MT + r) * 3 + p]
                + __ldg(b2 + head * DOUT + p);
        out[(size_t)(m0 + r) * (NHEADS * DOUT) + head * DOUT + p] = v;
    }
}

// ---------------- launch ----------------
extern "C" void kernel_launch(void* const* d_in, const int* in_sizes, int n_in,
                              void* d_out, int out_size) {
    const float* total_feat = (const float*)d_in[0];
    const float* W1 = (const float*)d_in[1];
    const float* b1 = (const float*)d_in[2];
    const float* W2 = (const float*)d_in[3];
    const float* b2 = (const float*)d_in[4];
    float* out = (float*)d_out;

    int total = NA4 + NW4;
    k_prep<<<(total + 255) / 256, 256>>>(total_feat, W1);

    cudaFuncSetAttribute(mano_gemm, cudaFuncAttributeMaxDynamicSharedMemorySize, SMEM_TOTAL);
    mano_gemm<<<dim3(NHEADS, BATCH / MT), NTH, SMEM_TOTAL>>>(b1, W2, b2, out);
}